// round 15
// baseline (speedup 1.0000x reference)
#include <cuda_runtime.h>
#include <cuda_fp16.h>
#include <math.h>

#define NEGV (-1e30f)

constexpr int C        = 256;
constexpr int LMAX     = 128;
constexpr int THREADS  = 512;   // 16 warps
constexpr int MAXB     = 64;
constexpr int PCH      = 40;    // halves per p chunk slot (64B data + 16B pad) -> conflict-free
constexpr int GRID_PAD = 148;

__device__ float g_f  [MAXB][C];
__device__ float g_g  [MAXB][C];
__device__ float g_a  [MAXB][LMAX];
__device__ float g_bt [MAXB][LMAX];
__device__ float g_lsf[MAXB];
__device__ float g_lsg[MAXB];
__device__ int   g_bar = 0;     // last-CTA ticket; reset by the combiner every call

struct SmemLayout {
  __half p16[2][8 * PCH];         // fp16 p, padded 8-chunk layout, double-buffered (1.3KB)
  float  xt[2][C];                // x_t tiles for numerator gather
  float  nb[2][LMAX + 2];         // numerator DP (log domain)
  float  red[16];                 // per-warp w sums (1-lag normalizer)
  float  sc[MAXB];                // per-batch scores (combine phase)
  int    labs[LMAX];
  int    amLast;
};

__device__ __forceinline__ float lse2_fast(float a, float b) {
  float mx = fmaxf(a, b);
  float mn = fminf(a, b);
  return mx + __logf(1.0f + __expf(mn - mx));
}

__device__ __forceinline__ __half2 shfl_h2(__half2 v, int o) {
  unsigned u = *reinterpret_cast<unsigned*>(&v);
  u = __shfl_xor_sync(0xffffffffu, u, o);
  return *reinterpret_cast<__half2*>(&u);
}

__global__ void __launch_bounds__(THREADS, 1)
chain_kernel(const float* __restrict__ x, const float* __restrict__ trans,
             const int* __restrict__ labels, const int* __restrict__ durations,
             int T, int L, int nwork, int grid, int B,
             float* __restrict__ out, int out_size)
{
  extern __shared__ char smraw[];
  SmemLayout& sm = *reinterpret_cast<SmemLayout*>(smraw);

  const int  tid  = threadIdx.x;
  const int  lane = tid & 31;
  const int  w    = tid >> 5;

  if (blockIdx.x < (unsigned)nwork) {
    const int  b    = blockIdx.x >> 1;
    const bool bwd  = blockIdx.x & 1;

    const int jq = w * 4 + (lane >> 3);   // j-quad 0..63
    const int h  = lane & 7;              // c-eighth (32 c each)
    const int j0 = 4 * jq;                // this thread's 4 j: j0..j0+3
    const int cbase = h * 32;

    const int D      = durations[b];
    const int m      = D >> 1;
    const int nsteps = bwd ? (D - 1 - m) : m;
    const int dt     = bwd ? -1 : 1;
    const int t0     = bwd ? (D - 1) : 1;     // t_k = t0 + dt*k

    // ---- M slice in fp16 registers: 32 c (c-paired half2) x 4 j = 64 regs
    __half2 mJ[4][16];
    #pragma unroll
    for (int jj = 0; jj < 4; ++jj) {
      int j = j0 + jj;
      #pragma unroll
      for (int k = 0; k < 16; ++k) {
        int c0 = cbase + 2 * k, c1 = c0 + 1;
        float v0, v1;
        if (!bwd) { v0 = __expf(trans[c0 * C + j]); v1 = __expf(trans[c1 * C + j]); }
        else      { v0 = __expf(trans[j * C + c0]); v1 = __expf(trans[j * C + c1]); }
        mJ[jj][k] = __floats2half2_rn(v0, v1);
      }
    }
    for (int l = tid; l < L; l += THREADS) sm.labs[l] = labels[b * L + l];

    const float* xb = x + (size_t)b * T * C;

    // write offset for this thread's 4 j (contiguous within one chunk)
    const int pwroff = PCH * (j0 >> 5) + (j0 & 31);

    // ---- init p (h==0 lanes write), xt, nb, red
    {
      float rv = 0.0f;
      if (h == 0) {
        int tp = bwd ? (D - 1) : 0;
        float w0 = __expf(xb[(size_t)tp * C + j0 + 0]);
        float w1 = __expf(xb[(size_t)tp * C + j0 + 1]);
        float w2 = __expf(xb[(size_t)tp * C + j0 + 2]);
        float w3 = __expf(xb[(size_t)tp * C + j0 + 3]);
        __half2 hv0 = __floats2half2_rn(w0, w1);
        __half2 hv1 = __floats2half2_rn(w2, w3);
        *reinterpret_cast<__half2*>(&sm.p16[0][pwroff])     = hv0;
        *reinterpret_cast<__half2*>(&sm.p16[0][pwroff + 2]) = hv1;
        rv = (w0 + w1) + (w2 + w3);
      }
      rv += __shfl_xor_sync(0xffffffffu, rv, 8);
      rv += __shfl_xor_sync(0xffffffffu, rv, 16);
      if (lane == 0) sm.red[w] = rv;
    }
    if (tid < C) sm.xt[0][tid] = xb[(size_t)t0 * C + tid];
    if (tid < LMAX + 2) { sm.nb[0][tid] = NEGV; sm.nb[1][tid] = NEGV; }
    __syncthreads();
    if (tid == 0) {
      if (!bwd) sm.nb[0][1] = xb[sm.labs[0]];
      else      sm.nb[0][L] = 0.0f;
    }

    // ---- two-step-ahead x + exp(x) pipelines (float4 at j0)
    auto ldx = [&](int k) -> float4 {
      int tp = t0 + dt * k;
      tp = max(0, min(tp, T - 1));
      return *reinterpret_cast<const float4*>(xb + (size_t)tp * C + j0);
    };
    float4 xq0 = ldx(0);
    float4 xq1 = ldx(1);
    float4 exq0 = make_float4(__expf(xq0.x), __expf(xq0.y), __expf(xq0.z), __expf(xq0.w));
    float4 exq1 = make_float4(__expf(xq1.x), __expf(xq1.y), __expf(xq1.z), __expf(xq1.w));

    float logS = 0.0f;
    int   cur  = 0;
    float wn[4] = {0, 0, 0, 0};

    // numerator: lanes h in {1,2} handle l = 2*jq + (h-1)
    const bool isnum = (h == 1 || h == 2) && (2 * jq + (h - 1)) < L;
    const int  lnum  = 2 * jq + (h - 1);
    int lab0 = 0, lab1 = -1;
    if (isnum) {
      lab0 = sm.labs[lnum];
      lab1 = (lnum + 1 < L) ? sm.labs[lnum + 1] : -1;
    }

    const int prdoff = PCH * h;   // this h's chunk (80h bytes, 16B aligned)

    for (int k = 0; k < nsteps; ++k) {
      __syncthreads();   // p16[cur], xt[cur], nb[cur], red visible
      const bool more = (k + 1) < nsteps;
      const int  nxt  = cur ^ 1;

      // ---- lagged normalizer (previous step's sum); latency-hidden under GEMV
      float S = sm.red[lane & 15];
      #pragma unroll
      for (int o = 8; o; o >>= 1) S += __shfl_xor_sync(0xffffffffu, S, o);
      float rs = __fdividef(1.0f, S);

      float4 xq2 = ldx(k + 2);   // consumed at step k+2

      // ---- GEMV: 4 LDS.128 of p (1 wavefront each) + 64 HFMA2 (8 chains of depth 8)
      const uint4* ph = reinterpret_cast<const uint4*>(sm.p16[cur] + prdoff);
      __half2 z = __float2half2_rn(0.0f);
      __half2 accA[4] = {z, z, z, z};
      __half2 accB[4] = {z, z, z, z};
      #pragma unroll
      for (int i = 0; i < 4; ++i) {
        uint4 pm = ph[i];
        const __half2* p2 = reinterpret_cast<const __half2*>(&pm);
        #pragma unroll
        for (int jj = 0; jj < 4; ++jj) {
          accA[jj] = __hfma2(p2[0], mJ[jj][4 * i + 0], accA[jj]);
          accB[jj] = __hfma2(p2[1], mJ[jj][4 * i + 1], accB[jj]);
          accA[jj] = __hfma2(p2[2], mJ[jj][4 * i + 2], accA[jj]);
          accB[jj] = __hfma2(p2[3], mJ[jj][4 * i + 3], accB[jj]);
        }
      }
      __half2 acc[4];
      #pragma unroll
      for (int jj = 0; jj < 4; ++jj) acc[jj] = __hadd2(accA[jj], accB[jj]);

      // ---- h-reduce: packed-half2 butterfly over the 8-lane group (depth 3)
      #pragma unroll
      for (int o = 1; o <= 4; o <<= 1) {
        #pragma unroll
        for (int jj = 0; jj < 4; ++jj)
          acc[jj] = __hadd2(acc[jj], shfl_h2(acc[jj], o));
      }
      float y[4];
      #pragma unroll
      for (int jj = 0; jj < 4; ++jj) {
        float2 f = __half22float2(acc[jj]);
        y[jj] = f.x + f.y;
      }

      // ---- wn: pure FMA tail (exp factors precomputed 2 steps ago)
      if (!bwd) {
        wn[0] = y[0] * exq0.x * rs;
        wn[1] = y[1] * exq0.y * rs;
        wn[2] = y[2] * exq0.z * rs;
        wn[3] = y[3] * exq0.w * rs;
      } else {
        wn[0] = y[0] * rs;  wn[1] = y[1] * rs;
        wn[2] = y[2] * rs;  wn[3] = y[3] * rs;
        if (more) {
          wn[0] *= exq1.x;  wn[1] *= exq1.y;
          wn[2] *= exq1.z;  wn[3] *= exq1.w;
        }
      }
      float rv = 0.0f;
      if (h == 0) {
        *reinterpret_cast<__half2*>(&sm.p16[nxt][pwroff]) =
            __floats2half2_rn(wn[0], wn[1]);
        *reinterpret_cast<__half2*>(&sm.p16[nxt][pwroff + 2]) =
            __floats2half2_rn(wn[2], wn[3]);
        rv = (wn[0] + wn[1]) + (wn[2] + wn[3]);
      }
      rv += __shfl_xor_sync(0xffffffffu, rv, 8);
      rv += __shfl_xor_sync(0xffffffffu, rv, 16);
      if (lane == 0) sm.red[w] = rv;

      if (h == 3 && more)
        *reinterpret_cast<float4*>(&sm.xt[nxt][j0]) = xq1;   // x[t_{k+1}]

      if (isnum) {
        int l = lnum;
        float nnew;
        if (!bwd) {
          float e = sm.xt[cur][lab0];
          nnew = lse2_fast(sm.nb[cur][l + 1], sm.nb[cur][l]) + e;
        } else {
          float v0 = sm.nb[cur][l + 1] + sm.xt[cur][lab0];
          float v1 = NEGV;
          if (lab1 >= 0) v1 = sm.nb[cur][l + 2] + sm.xt[cur][lab1];
          nnew = lse2_fast(v0, v1);
        }
        sm.nb[nxt][l + 1] = nnew;
      }

      if (tid == 0) logS += __logf(S);

      // ---- pipeline rotation; exp issues here, completes under the barrier
      float4 exq2 = make_float4(__expf(xq2.x), __expf(xq2.y),
                                __expf(xq2.z), __expf(xq2.w));
      xq0 = xq1;   xq1 = xq2;
      exq0 = exq1; exq1 = exq2;
      cur ^= 1;
    }
    __syncthreads();

    float Sf = sm.red[lane & 15];
    #pragma unroll
    for (int o = 8; o; o >>= 1) Sf += __shfl_xor_sync(0xffffffffu, Sf, o);

    if (!bwd) {
      if (h == 0) {
        float4 fv = make_float4(wn[0] / Sf, wn[1] / Sf, wn[2] / Sf, wn[3] / Sf);
        *reinterpret_cast<float4*>(&g_f[b][j0]) = fv;
      }
      if (tid < L)  g_a[b][tid] = sm.nb[cur][tid + 1];
      if (tid == 0) g_lsf[b] = logS + logf(Sf);
    } else {
      if (h == 0) {
        float4 fv = make_float4(wn[0] / Sf, wn[1] / Sf, wn[2] / Sf, wn[3] / Sf);
        *reinterpret_cast<float4*>(&g_g[b][j0]) = fv;
      }
      if (tid < L)  g_bt[b][tid] = sm.nb[cur][tid + 1];
      if (tid == 0) g_lsg[b] = logS + logf(Sf);
    }
    __syncthreads();
  }

  // ---- last-CTA-done: the final arriver performs the combine ----
  if (tid == 0) {
    __threadfence();                       // release g_f/g_a/g_lsf...
    int ticket = atomicAdd(&g_bar, 1);
    sm.amLast = (ticket == grid - 1);
  }
  __syncthreads();
  if (!sm.amLast) return;
  __threadfence();                         // acquire others' writes

  // combine (512 threads, warp per batch)
  for (int b2 = w; b2 < B; b2 += 16) {
    float dot = 0.0f;
    for (int c = lane; c < C; c += 32) dot += g_f[b2][c] * g_g[b2][c];
    #pragma unroll
    for (int o = 16; o; o >>= 1) dot += __shfl_xor_sync(0xffffffffu, dot, o);

    float mx = -INFINITY;
    for (int l = lane; l < L; l += 32) mx = fmaxf(mx, g_a[b2][l] + g_bt[b2][l]);
    #pragma unroll
    for (int o = 16; o; o >>= 1) mx = fmaxf(mx, __shfl_xor_sync(0xffffffffu, mx, o));

    float s = 0.0f;
    for (int l = lane; l < L; l += 32) s += expf(g_a[b2][l] + g_bt[b2][l] - mx);
    #pragma unroll
    for (int o = 16; o; o >>= 1) s += __shfl_xor_sync(0xffffffffu, s, o);

    if (lane == 0) {
      float num = mx + logf(s);
      float den = logf(dot) + g_lsf[b2] + g_lsg[b2];
      sm.sc[b2] = num - den;
    }
  }
  __syncthreads();
  if (tid == 0) {
    float tot = 0.0f;
    for (int i = 0; i < B; ++i) tot += sm.sc[i];   // fixed order => deterministic
    long long fr = 0;
    for (int i = 0; i < B; ++i) fr += durations[i];
    out[0] = tot;
    if (out_size > 1) out[1] = (float)fr;
    if (out_size > 2) out[2] = (float)fr;
    g_bar = 0;                                     // reset for next (graph) call
    __threadfence();
  }
}

extern "C" void kernel_launch(void* const* d_in, const int* in_sizes, int n_in,
                              void* d_out, int out_size)
{
  const float* x      = (const float*)d_in[0];
  const float* trans  = (const float*)d_in[1];
  const int*   labels = (const int*)d_in[2];
  const int*   dur    = (const int*)d_in[3];

  int B = in_sizes[3];
  int L = in_sizes[2] / B;
  int T = in_sizes[0] / (B * C);
  int nwork = 2 * B;
  int grid  = nwork < GRID_PAD ? GRID_PAD : nwork;

  size_t smem = sizeof(SmemLayout);
  cudaFuncSetAttribute(chain_kernel, cudaFuncAttributeMaxDynamicSharedMemorySize, (int)smem);

  chain_kernel<<<grid, THREADS, smem>>>(x, trans, labels, dur, T, L,
                                        nwork, grid, B, (float*)d_out, out_size);
}